// round 1
// baseline (speedup 1.0000x reference)
#include <cuda_runtime.h>
#include <math.h>

#define EDGES 65536
#define NATOM 2048
#define NRADB 24
#define NCOMP 5          // 120 = 24*5 radial outputs
#define KTOT 69
#define NFEAT 216        // 24*(1+2*4)
#define NELEM 94
#define EMBD 16
#define H1D 256
#define H2D 128
#define MAXG 256         // upper bound on species groups (actual <= 222)

// ---------------- scratch (static device globals; no allocation) ------------
__device__ float d_radial[EDGES * 120];      // per-edge radial MLP output
__device__ float d_gij[EDGES * KTOT];        // per-edge angular factors
__device__ float d_feat[NATOM * NFEAT];      // per-atom descriptors
__device__ float d_embS[NELEM * EMBD];       // per-species embedding
__device__ float d_B[NFEAT * NELEM * H1D];   // collapsed first-layer weights B[f][s][o]
__device__ int   d_counts[NELEM];
__device__ int   d_offsets[NELEM + 1];
__device__ int   d_atom_order[NATOM];
__device__ int   d_grp_s[MAXG], d_grp_start[MAXG], d_grp_cnt[MAXG];
__device__ int   d_ngroups;
__device__ double d_partial[MAXG];

// ---------------- helpers ----------------
__device__ __forceinline__ float silu(float x) {
    return x / (1.0f + expf(-x));
}

__device__ constexpr float ffact(int n) {
    return (n <= 1) ? 1.0f : (float)n * ffact(n - 1);
}

// ============================================================================
// K1: per-edge radial MLP + angular factors
// ============================================================================
__global__ void __launch_bounds__(128) k_edge(
    const float* __restrict__ rij,
    const float* __restrict__ Wr1, const float* __restrict__ br1,
    const float* __restrict__ Wr2, const float* __restrict__ br2)
{
    __shared__ float sW1[24 * 64];
    __shared__ float sB1[64];
    __shared__ float sW2[64 * 120];
    __shared__ float sB2[120];
    int tid = threadIdx.x;
    for (int i = tid; i < 24 * 64; i += 128) sW1[i] = Wr1[i];
    for (int i = tid; i < 64;      i += 128) sB1[i] = br1[i];
    for (int i = tid; i < 64 * 120; i += 128) sW2[i] = Wr2[i];
    for (int i = tid; i < 120;     i += 128) sB2[i] = br2[i];
    __syncthreads();

    int e = blockIdx.x * 128 + tid;
    if (e >= EDGES) return;

    float x = rij[e * 3 + 0], y = rij[e * 3 + 1], z = rij[e * 3 + 2];
    float r = sqrtf(x * x + y * y + z * z);
    float inv = 1.0f / r;
    float ux = x * inv, uy = y * inv, uz = z * inv;

    float rc = fminf(r, 6.0f);
    float fc = 0.5f * (cospif(rc * (1.0f / 6.0f)) + 1.0f);

    float basis[24];
#pragma unroll
    for (int i = 0; i < 24; i++) {
        float d = r - (float)i * (6.0f / 23.0f);
        basis[i] = expf(-d * d * 8.0f) * fc;   // width = 0.25 -> 1/(2w^2)=8
    }

    // layer 1: 24 -> 64, silu
    float h[64];
#pragma unroll
    for (int j4 = 0; j4 < 16; j4++) {
        float4 acc = *(const float4*)(&sB1[j4 * 4]);
#pragma unroll
        for (int i = 0; i < 24; i++) {
            float4 w = *(const float4*)(&sW1[i * 64 + j4 * 4]);
            acc.x += basis[i] * w.x; acc.y += basis[i] * w.y;
            acc.z += basis[i] * w.z; acc.w += basis[i] * w.w;
        }
        h[j4 * 4 + 0] = silu(acc.x); h[j4 * 4 + 1] = silu(acc.y);
        h[j4 * 4 + 2] = silu(acc.z); h[j4 * 4 + 3] = silu(acc.w);
    }

    // layer 2: 64 -> 120, silu ; write [E,120]
    float* out = &d_radial[(size_t)e * 120];
#pragma unroll
    for (int o4 = 0; o4 < 30; o4++) {
        float4 acc = *(const float4*)(&sB2[o4 * 4]);
#pragma unroll
        for (int j = 0; j < 64; j++) {
            float4 w = *(const float4*)(&sW2[j * 120 + o4 * 4]);
            acc.x += h[j] * w.x; acc.y += h[j] * w.y;
            acc.z += h[j] * w.z; acc.w += h[j] * w.w;
        }
        float4 o;
        o.x = silu(acc.x); o.y = silu(acc.y); o.z = silu(acc.z); o.w = silu(acc.w);
        *(float4*)(&out[o4 * 4]) = o;
    }

    // angular factors g_ij[k] = prod (u+eps)^L * fnorm ; tables fully unrolled
    float px[5], py[5], pz[5];
    px[0] = 1.0f; px[1] = ux + 1e-12f; px[2] = px[1] * px[1]; px[3] = px[2] * px[1]; px[4] = px[2] * px[2];
    py[0] = 1.0f; py[1] = uy + 1e-12f; py[2] = py[1] * py[1]; py[3] = py[2] * py[1]; py[4] = py[2] * py[2];
    pz[0] = 1.0f; pz[1] = uz + 1e-12f; pz[2] = pz[1] * pz[1]; pz[3] = pz[2] * pz[1]; pz[4] = pz[2] * pz[2];

    float* go = &d_gij[(size_t)e * KTOT];
    int k = 0;
#pragma unroll
    for (int zz = 1; zz <= 4; zz++) {
#pragma unroll
        for (int n = 0; n <= zz; n++) {
#pragma unroll
            for (int lx = 0; lx <= n; lx++) {
#pragma unroll
                for (int ly = 0; ly <= n - lx; ly++) {
                    int lz = n - lx - ly;
                    float fn = ffact(zz) / (ffact(zz - n) * ffact(lx) * ffact(ly) * ffact(lz));
                    go[k] = px[lx] * py[ly] * pz[lz] * fn;
                    k++;
                }
            }
        }
    }
}

// ============================================================================
// K2: per-atom segmented reduction + descriptor assembly
// acc layout: [0,24) two-body per rad ; [24,1680): 24 + k*24 + rad
// ============================================================================
template <int Z>
__device__ __forceinline__ float zsum(const float* sgi, int rad, int sflag, int koff) {
    float sum = 0.0f;
    int k = koff;
#pragma unroll
    for (int n = 0; n <= Z; n++) {
        float lam = (n & 1) ? -1.0f : 1.0f;
#pragma unroll
        for (int lx = 0; lx <= n; lx++) {
#pragma unroll
            for (int ly = 0; ly <= n - lx; ly++) {
                float g = sgi[24 + k * 24 + rad];
                float g2 = g * g;
                sum += sflag ? g2 * lam : g2;
                k++;
            }
        }
    }
    return sum * (1.0f / (float)(1 << (Z - 1)));   // 2^(1-Z)
}

__global__ void __launch_bounds__(256) k_atom(const int* __restrict__ fai)
{
    __shared__ int s_lo, s_hi;
    __shared__ float sr[120];
    __shared__ float sg[KTOT];
    __shared__ float sgi[1680];

    int a = blockIdx.x;
    int tid = threadIdx.x;

    if (tid == 0) {
        int lo = 0, hi = EDGES;
        while (lo < hi) { int m = (lo + hi) >> 1; if (fai[m] < a) lo = m + 1; else hi = m; }
        s_lo = lo;
        int lo2 = lo, hi2 = EDGES;
        while (lo2 < hi2) { int m = (lo2 + hi2) >> 1; if (fai[m] < a + 1) lo2 = m + 1; else hi2 = m; }
        s_hi = lo2;
    }
    __syncthreads();
    int lo = s_lo, hi = s_hi;

    float acc[7];
    int ridx[7], kk[7];
    bool istb[7], valid[7];
#pragma unroll
    for (int jj = 0; jj < 7; jj++) {
        int ai = tid + jj * 256;
        valid[jj] = (ai < 1680);
        acc[jj] = 0.0f;
        if (ai < 24) { istb[jj] = true;  ridx[jj] = ai * 5; kk[jj] = 0; }
        else {
            istb[jj] = false;
            int t = ai - 24;
            int k = t / 24;
            int rad = t - k * 24;
            int comp = (k < 4) ? 1 : (k < 14) ? 2 : (k < 34) ? 3 : 4;
            ridx[jj] = rad * 5 + comp;
            kk[jj] = k;
        }
    }

    for (int e = lo; e < hi; e++) {
        if (tid < 120) sr[tid] = d_radial[(size_t)e * 120 + tid];
        else if (tid < 120 + KTOT) sg[tid - 120] = d_gij[(size_t)e * KTOT + (tid - 120)];
        __syncthreads();
#pragma unroll
        for (int jj = 0; jj < 7; jj++) {
            if (valid[jj]) acc[jj] += istb[jj] ? sr[ridx[jj]] : sr[ridx[jj]] * sg[kk[jj]];
        }
        __syncthreads();
    }

#pragma unroll
    for (int jj = 0; jj < 7; jj++)
        if (valid[jj]) sgi[tid + jj * 256] = acc[jj];
    __syncthreads();

    if (tid < NFEAT) {
        float v;
        if (tid < 24) {
            v = sgi[tid];
        } else {
            int t = tid - 24;
            int iz = t / 48;
            int sflag = (t / 24) & 1;
            int rad = t % 24;
            if (iz == 0)      v = zsum<1>(sgi, rad, sflag, 0);
            else if (iz == 1) v = zsum<2>(sgi, rad, sflag, 4);
            else if (iz == 2) v = zsum<3>(sgi, rad, sflag, 14);
            else              v = zsum<4>(sgi, rad, sflag, 34);
        }
        d_feat[a * NFEAT + tid] = v;
    }
}

// ============================================================================
// species embedding (94 distinct) + collapsed first-layer weights B[f][s][o]
// ============================================================================
__global__ void k_embS(const float* __restrict__ Ws1, const float* __restrict__ bs1,
                       const float* __restrict__ Ws2, const float* __restrict__ bs2)
{
    int s = blockIdx.x;
    int t = threadIdx.x;   // 32 threads
    __shared__ float hh[32];
    hh[t] = silu(Ws1[s * 32 + t] + bs1[t]);
    __syncwarp();
    if (t < EMBD) {
        float a = bs2[t];
#pragma unroll
        for (int j = 0; j < 32; j++) a += hh[j] * Ws2[j * EMBD + t];
        d_embS[s * EMBD + t] = a;
    }
}

__global__ void __launch_bounds__(256) k_B(const float* __restrict__ Wa1)
{
    int f = blockIdx.x;      // 216 blocks
    int tid = threadIdx.x;   // 256 outputs
    __shared__ float sW[16 * 256];
    __shared__ float sE[NELEM * EMBD];
    for (int i = tid; i < 16 * 256; i += 256) sW[i] = Wa1[(size_t)(f * 16) * 256 + i];
    for (int i = tid; i < NELEM * EMBD; i += 256) sE[i] = d_embS[i];
    __syncthreads();
    for (int s = 0; s < NELEM; s++) {
        float acc = 0.0f;
#pragma unroll
        for (int m = 0; m < EMBD; m++) acc += sE[s * EMBD + m] * sW[m * 256 + tid];
        d_B[((size_t)f * NELEM + s) * H1D + tid] = acc;
    }
}

// ============================================================================
// deterministic species grouping
// ============================================================================
__global__ void k_zero() {
    int t = threadIdx.x;
    if (t < NELEM) d_counts[t] = 0;
}

__global__ void k_count(const int* __restrict__ sp) {
    int a = blockIdx.x * 256 + threadIdx.x;
    if (a < NATOM) atomicAdd(&d_counts[sp[a]], 1);
}

__global__ void k_scan() {
    if (threadIdx.x || blockIdx.x) return;
    int off = 0;
    for (int s = 0; s < NELEM; s++) { d_offsets[s] = off; off += d_counts[s]; }
    d_offsets[NELEM] = off;
    int ng = 0;
    for (int s = 0; s < NELEM; s++) {
        int c = d_counts[s];
        for (int ch = 0; ch < c; ch += 16) {
            d_grp_s[ng] = s;
            d_grp_start[ng] = d_offsets[s] + ch;
            d_grp_cnt[ng] = min(16, c - ch);
            ng++;
        }
    }
    d_ngroups = ng;
    for (int g = 0; g < MAXG; g++) d_partial[g] = 0.0;
}

__global__ void k_rank(const int* __restrict__ sp) {
    int a = blockIdx.x * 256 + threadIdx.x;
    if (a >= NATOM) return;
    int s = sp[a];
    int r = 0;
    for (int j = 0; j < a; j++) r += (sp[j] == s);
    d_atom_order[d_offsets[s] + r] = a;
}

// ============================================================================
// head MLP: h1 = silu(feat @ B_s + ba1); h2 = silu(h1 @ Wa2 + ba2); e = h2.Wa3+ba3
// one block per species group (<=16 atoms, same species)
// ============================================================================
__global__ void __launch_bounds__(256) k_head(
    const float* __restrict__ ba1,
    const float* __restrict__ Wa2, const float* __restrict__ ba2,
    const float* __restrict__ Wa3, const float* __restrict__ ba3)
{
    int g = blockIdx.x;
    if (g >= d_ngroups) return;
    int tid = threadIdx.x;

    __shared__ float sfeat[16 * NFEAT];
    __shared__ float sh1[16 * H1D];
    __shared__ float sh2[16 * H2D];
    __shared__ double se[16];
    __shared__ int satom[16];

    int s = d_grp_s[g], start = d_grp_start[g], cnt = d_grp_cnt[g];
    if (tid < 16) satom[tid] = (tid < cnt) ? d_atom_order[start + tid] : -1;
    __syncthreads();

    for (int i = tid; i < 16 * NFEAT; i += 256) {
        int al = i / NFEAT, f = i - al * NFEAT;
        sfeat[i] = (al < cnt) ? d_feat[(size_t)satom[al] * NFEAT + f] : 0.0f;
    }
    __syncthreads();

    float acc[16];
    float b1 = ba1[tid];
#pragma unroll
    for (int a2 = 0; a2 < 16; a2++) acc[a2] = b1;

    for (int f = 0; f < NFEAT; f++) {
        float bw = d_B[((size_t)f * NELEM + s) * H1D + tid];
#pragma unroll
        for (int a2 = 0; a2 < 16; a2++) acc[a2] += sfeat[a2 * NFEAT + f] * bw;
    }
#pragma unroll
    for (int a2 = 0; a2 < 16; a2++) sh1[a2 * H1D + tid] = silu(acc[a2]);
    __syncthreads();

    // layer 2: 256 -> 128
#pragma unroll
    for (int it = 0; it < 8; it++) {
        int t = tid + it * 256;
        int a2 = t >> 7;
        int o = t & 127;
        float a2c = ba2[o];
        for (int j = 0; j < H1D; j++) a2c += sh1[a2 * H1D + j] * Wa2[j * H2D + o];
        sh2[a2 * H2D + o] = silu(a2c);
    }
    __syncthreads();

    if (tid < 16) {
        double ev = 0.0;
        if (tid < cnt) {
            float e3 = ba3[0];
            for (int j = 0; j < H2D; j++) e3 += sh2[tid * H2D + j] * Wa3[j];
            ev = (double)e3;
        }
        se[tid] = ev;
    }
    __syncthreads();
    if (tid == 0) {
        double ssum = 0.0;
        for (int i = 0; i < 16; i++) ssum += se[i];
        d_partial[g] = ssum;
    }
}

__global__ void k_final(float* out) {
    if (threadIdx.x == 0 && blockIdx.x == 0) {
        double ssum = 0.0;
        for (int g = 0; g < MAXG; g++) ssum += d_partial[g];
        out[0] = (float)ssum;
    }
}

// ============================================================================
extern "C" void kernel_launch(void* const* d_in, const int* in_sizes, int n_in,
                              void* d_out, int out_size)
{
    const float* rij = (const float*)d_in[0];
    const float* Wr1 = (const float*)d_in[1];
    const float* br1 = (const float*)d_in[2];
    const float* Wr2 = (const float*)d_in[3];
    const float* br2 = (const float*)d_in[4];
    const float* Ws1 = (const float*)d_in[5];
    const float* bs1 = (const float*)d_in[6];
    const float* Ws2 = (const float*)d_in[7];
    const float* bs2 = (const float*)d_in[8];
    const float* Wa1 = (const float*)d_in[9];
    const float* ba1 = (const float*)d_in[10];
    const float* Wa2 = (const float*)d_in[11];
    const float* ba2 = (const float*)d_in[12];
    const float* Wa3 = (const float*)d_in[13];
    const float* ba3 = (const float*)d_in[14];
    const int* fai = (const int*)d_in[15];
    const int* species = (const int*)d_in[16];
    float* out = (float*)d_out;

    k_edge<<<EDGES / 128, 128>>>(rij, Wr1, br1, Wr2, br2);
    k_embS<<<NELEM, 32>>>(Ws1, bs1, Ws2, bs2);
    k_B<<<NFEAT, 256>>>(Wa1);
    k_zero<<<1, 128>>>();
    k_count<<<(NATOM + 255) / 256, 256>>>(species);
    k_scan<<<1, 1>>>();
    k_rank<<<(NATOM + 255) / 256, 256>>>(species);
    k_atom<<<NATOM, 256>>>(fai);
    k_head<<<MAXG, 256>>>(ba1, Wa2, ba2, Wa3, ba3);
    k_final<<<1, 1>>>(out);
}

// round 2
// speedup vs baseline: 1.2604x; 1.2604x over previous
#include <cuda_runtime.h>
#include <math.h>

#define EDGES 65536
#define NATOM 2048
#define KTOT 69
#define NFEAT 216
#define NELEM 94
#define EMBD 16
#define H1D 256
#define H2D 128
#define MAXG 256
#define NACC 1680

// ---------------- scratch ----------------
__device__ __align__(16) float d_radial[EDGES * 120];
__device__ __align__(16) float d_gij[EDGES * KTOT];
__device__ __align__(16) float d_feat[NATOM * NFEAT];
__device__ float d_embS[NELEM * EMBD];
__device__ __align__(16) float d_B[(size_t)NELEM * NFEAT * H1D]; // [s][f][o]
__device__ int   d_offsets[NELEM + 1];
__device__ int   d_atom_order[NATOM];
__device__ int   d_grp_s[MAXG], d_grp_start[MAXG], d_grp_cnt[MAXG];
__device__ int   d_ngroups;
__device__ double d_partial[MAXG];

// ---------------- packed fp32x2 helpers (sm_103a) ----------------
typedef unsigned long long u64;

__device__ __forceinline__ u64 splat2(float v) {
    u64 r; unsigned int u = __float_as_uint(v);
    asm("mov.b64 %0, {%1, %1};" : "=l"(r) : "r"(u));
    return r;
}
__device__ __forceinline__ void unpack2(u64 v, float& a, float& b) {
    unsigned int x, y;
    asm("mov.b64 {%0, %1}, %2;" : "=r"(x), "=r"(y) : "l"(v));
    a = __uint_as_float(x); b = __uint_as_float(y);
}
__device__ __forceinline__ void fma2(u64& d, u64 a, u64 b) {
    asm("fma.rn.f32x2 %0, %1, %2, %0;" : "+l"(d) : "l"(a), "l"(b));
}
__device__ __forceinline__ void add2(u64& d, u64 a) {
    asm("add.rn.f32x2 %0, %0, %1;" : "+l"(d) : "l"(a));
}

__device__ __forceinline__ float silu(float x) {
    return __fdividef(x, 1.0f + __expf(-x));
}

__device__ constexpr float ffact(int n) {
    return (n <= 1) ? 1.0f : (float)n * ffact(n - 1);
}

// ============================================================================
// K: per-edge radial MLP (f32x2) + angular factors
// ============================================================================
__global__ void __launch_bounds__(128) k_edge(
    const float* __restrict__ rij,
    const float* __restrict__ Wr1, const float* __restrict__ br1,
    const float* __restrict__ Wr2, const float* __restrict__ br2)
{
    __shared__ __align__(16) float sW1[24 * 64];
    __shared__ __align__(16) float sB1[64];
    __shared__ __align__(16) float sW2[64 * 120];
    __shared__ __align__(16) float sB2[120];
    int tid = threadIdx.x;
    for (int i = tid; i < 24 * 64; i += 128) sW1[i] = Wr1[i];
    for (int i = tid; i < 64;      i += 128) sB1[i] = br1[i];
    for (int i = tid; i < 64 * 120; i += 128) sW2[i] = Wr2[i];
    for (int i = tid; i < 120;     i += 128) sB2[i] = br2[i];
    __syncthreads();

    int e = blockIdx.x * 128 + tid;   // grid exactly covers EDGES

    float x = rij[e * 3 + 0], y = rij[e * 3 + 1], z = rij[e * 3 + 2];
    float r = sqrtf(x * x + y * y + z * z);
    float inv = 1.0f / r;
    float ux = x * inv, uy = y * inv, uz = z * inv;

    float rc = fminf(r, 6.0f);
    float fc = 0.5f * (cospif(rc * (1.0f / 6.0f)) + 1.0f);

    u64 bsp[24];
#pragma unroll
    for (int i = 0; i < 24; i++) {
        float d = r - (float)i * (6.0f / 23.0f);
        bsp[i] = splat2(__expf(-d * d * 8.0f) * fc);
    }

    // layer 1: 24 -> 64 via FFMA2, chunks of 8 outputs (fully unrolled)
    float h[64];
#pragma unroll
    for (int c8 = 0; c8 < 8; c8++) {
        const u64* bb = (const u64*)&sB1[c8 * 8];
        u64 a0 = bb[0], a1 = bb[1], a2 = bb[2], a3 = bb[3];
#pragma unroll
        for (int i = 0; i < 24; i++) {
            const ulonglong2* w = (const ulonglong2*)&sW1[i * 64 + c8 * 8];
            ulonglong2 w01 = w[0], w23 = w[1];
            fma2(a0, bsp[i], w01.x); fma2(a1, bsp[i], w01.y);
            fma2(a2, bsp[i], w23.x); fma2(a3, bsp[i], w23.y);
        }
        float f0, f1;
        unpack2(a0, f0, f1); h[c8*8+0] = silu(f0); h[c8*8+1] = silu(f1);
        unpack2(a1, f0, f1); h[c8*8+2] = silu(f0); h[c8*8+3] = silu(f1);
        unpack2(a2, f0, f1); h[c8*8+4] = silu(f0); h[c8*8+5] = silu(f1);
        unpack2(a3, f0, f1); h[c8*8+6] = silu(f0); h[c8*8+7] = silu(f1);
    }

    // layer 2: 64 -> 120, chunks of 8 outputs (outer not unrolled: code stays small)
    float* out = &d_radial[(size_t)e * 120];
#pragma unroll 1
    for (int c8 = 0; c8 < 15; c8++) {
        const u64* bb = (const u64*)&sB2[c8 * 8];
        u64 a0 = bb[0], a1 = bb[1], a2 = bb[2], a3 = bb[3];
#pragma unroll
        for (int j = 0; j < 64; j++) {
            u64 hs = splat2(h[j]);
            const ulonglong2* w = (const ulonglong2*)&sW2[j * 120 + c8 * 8];
            ulonglong2 w01 = w[0], w23 = w[1];
            fma2(a0, hs, w01.x); fma2(a1, hs, w01.y);
            fma2(a2, hs, w23.x); fma2(a3, hs, w23.y);
        }
        float f0, f1, f2, f3, f4, f5, f6, f7;
        unpack2(a0, f0, f1); unpack2(a1, f2, f3);
        unpack2(a2, f4, f5); unpack2(a3, f6, f7);
        float4 o0 = { silu(f0), silu(f1), silu(f2), silu(f3) };
        float4 o1 = { silu(f4), silu(f5), silu(f6), silu(f7) };
        *(float4*)&out[c8 * 8 + 0] = o0;
        *(float4*)&out[c8 * 8 + 4] = o1;
    }

    // angular factors
    float px[5], py[5], pz[5];
    px[0]=1.0f; px[1]=ux+1e-12f; px[2]=px[1]*px[1]; px[3]=px[2]*px[1]; px[4]=px[2]*px[2];
    py[0]=1.0f; py[1]=uy+1e-12f; py[2]=py[1]*py[1]; py[3]=py[2]*py[1]; py[4]=py[2]*py[2];
    pz[0]=1.0f; pz[1]=uz+1e-12f; pz[2]=pz[1]*pz[1]; pz[3]=pz[2]*pz[1]; pz[4]=pz[2]*pz[2];

    float* go = &d_gij[(size_t)e * KTOT];
    int k = 0;
#pragma unroll
    for (int zz = 1; zz <= 4; zz++) {
#pragma unroll
        for (int n = 0; n <= zz; n++) {
#pragma unroll
            for (int lx = 0; lx <= n; lx++) {
#pragma unroll
                for (int ly = 0; ly <= n - lx; ly++) {
                    int lz = n - lx - ly;
                    float fn = ffact(zz) / (ffact(zz - n) * ffact(lx) * ffact(ly) * ffact(lz));
                    go[k] = px[lx] * py[ly] * pz[lz] * fn;
                    k++;
                }
            }
        }
    }
}

// ============================================================================
// K: per-atom segmented reduction (16-edge tiles, f32x2) + descriptor assembly
// ============================================================================
template <int Z>
__device__ __forceinline__ float zsum(const float* sgi, int rad, int sflag, int koff) {
    float sum = 0.0f;
    int k = koff;
#pragma unroll
    for (int n = 0; n <= Z; n++) {
        float lam = (n & 1) ? -1.0f : 1.0f;
#pragma unroll
        for (int lx = 0; lx <= n; lx++) {
#pragma unroll
            for (int ly = 0; ly <= n - lx; ly++) {
                float g = sgi[24 + k * 24 + rad];
                float g2 = g * g;
                sum += sflag ? g2 * lam : g2;
                k++;
            }
        }
    }
    return sum * (1.0f / (float)(1 << (Z - 1)));
}

__global__ void __launch_bounds__(256) k_atom(const int* __restrict__ fai)
{
    __shared__ int s_lohi[2];
    __shared__ __align__(16) float sr[120 * 18];  // [c][ee] c=comp*24+rad, pad 18
    __shared__ __align__(16) float sg[KTOT * 18]; // [k][ee]
    __shared__ float sgi[NACC];

    int a = blockIdx.x;
    int tid = threadIdx.x;

    if (tid < 2) {
        int tgt = a + tid;
        int lo = 0, hi = EDGES;
        while (lo < hi) { int m = (lo + hi) >> 1; if (fai[m] < tgt) lo = m + 1; else hi = m; }
        s_lohi[tid] = lo;
    }
    __syncthreads();
    int lo = s_lohi[0], hi = s_lohi[1];

    // slot metadata (7 accumulators per thread)
    u64 acc2[7];
    int cIdx[7], kk[7];
    bool istb[7], valid[7];
#pragma unroll
    for (int jj = 0; jj < 7; jj++) {
        int ai = tid + jj * 256;
        valid[jj] = (ai < NACC);
        acc2[jj] = 0ull;
        if (ai < 24) { istb[jj] = true; cIdx[jj] = ai; kk[jj] = 0; }
        else {
            istb[jj] = false;
            int t = ai - 24;
            int k = t / 24;
            int rad = t - k * 24;
            int comp = (k < 4) ? 1 : (k < 14) ? 2 : (k < 34) ? 3 : 4;
            cIdx[jj] = comp * 24 + rad;
            kk[jj] = k;
        }
    }

    for (int e0 = lo; e0 < hi; e0 += 16) {
        // load 16 edges, transposed, zero-padded
        for (int i = tid; i < 16 * 120; i += 256) {
            int ee = i / 120;
            int m = i - ee * 120;            // rad*5+comp
            int c = (m % 5) * 24 + (m / 5);
            int e = e0 + ee;
            sr[c * 18 + ee] = (e < hi) ? d_radial[(size_t)e * 120 + m] : 0.0f;
        }
        for (int i = tid; i < 16 * KTOT; i += 256) {
            int ee = i / KTOT;
            int k = i - ee * KTOT;
            int e = e0 + ee;
            sg[k * 18 + ee] = (e < hi) ? d_gij[(size_t)e * KTOT + k] : 0.0f;
        }
        __syncthreads();

#pragma unroll
        for (int jj = 0; jj < 7; jj++) {
            if (!valid[jj]) continue;
            const u64* rp = (const u64*)&sr[cIdx[jj] * 18];
            if (istb[jj]) {
#pragma unroll
                for (int p = 0; p < 8; p++) add2(acc2[jj], rp[p]);
            } else {
                const u64* gp = (const u64*)&sg[kk[jj] * 18];
#pragma unroll
                for (int p = 0; p < 8; p++) fma2(acc2[jj], rp[p], gp[p]);
            }
        }
        __syncthreads();
    }

#pragma unroll
    for (int jj = 0; jj < 7; jj++) {
        if (valid[jj]) {
            float l0, l1; unpack2(acc2[jj], l0, l1);
            sgi[tid + jj * 256] = l0 + l1;
        }
    }
    __syncthreads();

    if (tid < NFEAT) {
        float v;
        if (tid < 24) v = sgi[tid];
        else {
            int t = tid - 24;
            int iz = t / 48;
            int sflag = (t / 24) & 1;
            int rad = t % 24;
            if (iz == 0)      v = zsum<1>(sgi, rad, sflag, 0);
            else if (iz == 1) v = zsum<2>(sgi, rad, sflag, 4);
            else if (iz == 2) v = zsum<3>(sgi, rad, sflag, 14);
            else              v = zsum<4>(sgi, rad, sflag, 34);
        }
        d_feat[a * NFEAT + tid] = v;
    }
}

// ============================================================================
// species embedding + collapsed first-layer weights B[s][f][o]
// ============================================================================
__global__ void k_embS(const float* __restrict__ Ws1, const float* __restrict__ bs1,
                       const float* __restrict__ Ws2, const float* __restrict__ bs2)
{
    int s = blockIdx.x;
    int t = threadIdx.x;   // 32
    __shared__ float hh[32];
    hh[t] = silu(Ws1[s * 32 + t] + bs1[t]);
    __syncwarp();
    if (t < EMBD) {
        float a = bs2[t];
#pragma unroll
        for (int j = 0; j < 32; j++) a += hh[j] * Ws2[j * EMBD + t];
        d_embS[s * EMBD + t] = a;
    }
}

__global__ void __launch_bounds__(256) k_B(const float* __restrict__ Wa1)
{
    int f = blockIdx.x;      // 216
    int tid = threadIdx.x;   // 256
    __shared__ float sW[16 * 256];
    __shared__ float sE[NELEM * EMBD];
    for (int i = tid; i < 16 * 256; i += 256) sW[i] = Wa1[(size_t)(f * 16) * 256 + i];
    for (int i = tid; i < NELEM * EMBD; i += 256) sE[i] = d_embS[i];
    __syncthreads();
    for (int s = 0; s < NELEM; s++) {
        float acc = 0.0f;
#pragma unroll
        for (int m = 0; m < EMBD; m++) acc += sE[s * EMBD + m] * sW[m * 256 + tid];
        d_B[((size_t)s * NFEAT + f) * H1D + tid] = acc;
    }
}

// ============================================================================
// deterministic species grouping (single block)
// ============================================================================
__global__ void __launch_bounds__(1024) k_group(const int* __restrict__ sp)
{
    __shared__ int cnt[NELEM];
    __shared__ int off[NELEM];
    __shared__ int ssp[NATOM];
    int tid = threadIdx.x;
    if (tid < NELEM) cnt[tid] = 0;
    for (int a = tid; a < NATOM; a += 1024) ssp[a] = sp[a];
    __syncthreads();
    for (int a = tid; a < NATOM; a += 1024) atomicAdd(&cnt[ssp[a]], 1);
    __syncthreads();
    if (tid == 0) {
        int o = 0, ng = 0;
        for (int s = 0; s < NELEM; s++) {
            off[s] = o; d_offsets[s] = o;
            int c = cnt[s];
            for (int ch = 0; ch < c; ch += 16) {
                d_grp_s[ng] = s; d_grp_start[ng] = o + ch;
                d_grp_cnt[ng] = min(16, c - ch); ng++;
            }
            o += c;
        }
        d_offsets[NELEM] = o;
        d_ngroups = ng;
    }
    for (int g = tid; g < MAXG; g += 1024) d_partial[g] = 0.0;
    __syncthreads();
    for (int a = tid; a < NATOM; a += 1024) {
        int s = ssp[a];
        int r = 0;
        for (int j = 0; j < a; j++) r += (ssp[j] == s);
        d_atom_order[off[s] + r] = a;
    }
}

// ============================================================================
// head MLP per species group (<=16 atoms)
// ============================================================================
__global__ void __launch_bounds__(256) k_head(
    const float* __restrict__ ba1,
    const float* __restrict__ Wa2, const float* __restrict__ ba2,
    const float* __restrict__ Wa3, const float* __restrict__ ba3)
{
    int g = blockIdx.x;
    if (g >= d_ngroups) return;
    int tid = threadIdx.x;

    __shared__ __align__(16) float sfeat[NFEAT * 18];  // [f][atom], pad 18
    __shared__ float sh1[16 * H1D];
    __shared__ float sh2[16 * H2D];
    __shared__ double se[16];
    __shared__ int satom[16];

    int s = d_grp_s[g], start = d_grp_start[g], cnt = d_grp_cnt[g];
    if (tid < 16) satom[tid] = (tid < cnt) ? d_atom_order[start + tid] : 0;
    __syncthreads();

    for (int i = tid; i < 16 * NFEAT; i += 256) {
        int al = i / NFEAT, f = i - al * NFEAT;
        sfeat[f * 18 + al] = (al < cnt) ? d_feat[(size_t)satom[al] * NFEAT + f] : 0.0f;
    }
    __syncthreads();

    // layer 1: 216 -> 256, 16 atoms as 8 f32x2 pairs
    u64 acc2[8];
    u64 binit = splat2(ba1[tid]);
#pragma unroll
    for (int p = 0; p < 8; p++) acc2[p] = binit;

    const float* Bs = &d_B[(size_t)s * NFEAT * H1D + tid];
#pragma unroll 4
    for (int f = 0; f < NFEAT; f++) {
        u64 bw = splat2(Bs[(size_t)f * H1D]);
        const u64* fp = (const u64*)&sfeat[f * 18];
#pragma unroll
        for (int p = 0; p < 8; p++) fma2(acc2[p], fp[p], bw);
    }
#pragma unroll
    for (int p = 0; p < 8; p++) {
        float lo, hi; unpack2(acc2[p], lo, hi);
        sh1[(2 * p) * H1D + tid] = silu(lo);
        sh1[(2 * p + 1) * H1D + tid] = silu(hi);
    }
    __syncthreads();

    // layer 2: 256 -> 128
#pragma unroll
    for (int it = 0; it < 8; it++) {
        int t = tid + it * 256;
        int a2 = t >> 7;
        int o = t & 127;
        float acc = ba2[o];
#pragma unroll 4
        for (int j = 0; j < H1D; j++) acc += sh1[a2 * H1D + j] * Wa2[j * H2D + o];
        sh2[a2 * H2D + o] = silu(acc);
    }
    __syncthreads();

    if (tid < 16) {
        double ev = 0.0;
        if (tid < cnt) {
            float e3 = ba3[0];
            for (int j = 0; j < H2D; j++) e3 += sh2[tid * H2D + j] * Wa3[j];
            ev = (double)e3;
        }
        se[tid] = ev;
    }
    __syncthreads();
    if (tid == 0) {
        double ssum = 0.0;
        for (int i = 0; i < 16; i++) ssum += se[i];
        d_partial[g] = ssum;
    }
}

__global__ void k_final(float* out) {
    int lane = threadIdx.x;
    double s = 0.0;
    for (int g = lane; g < MAXG; g += 32) s += d_partial[g];
#pragma unroll
    for (int o = 16; o > 0; o >>= 1) s += __shfl_down_sync(0xffffffffu, s, o);
    if (lane == 0) out[0] = (float)s;
}

// ============================================================================
extern "C" void kernel_launch(void* const* d_in, const int* in_sizes, int n_in,
                              void* d_out, int out_size)
{
    const float* rij = (const float*)d_in[0];
    const float* Wr1 = (const float*)d_in[1];
    const float* br1 = (const float*)d_in[2];
    const float* Wr2 = (const float*)d_in[3];
    const float* br2 = (const float*)d_in[4];
    const float* Ws1 = (const float*)d_in[5];
    const float* bs1 = (const float*)d_in[6];
    const float* Ws2 = (const float*)d_in[7];
    const float* bs2 = (const float*)d_in[8];
    const float* Wa1 = (const float*)d_in[9];
    const float* ba1 = (const float*)d_in[10];
    const float* Wa2 = (const float*)d_in[11];
    const float* ba2 = (const float*)d_in[12];
    const float* Wa3 = (const float*)d_in[13];
    const float* ba3 = (const float*)d_in[14];
    const int* fai = (const int*)d_in[15];
    const int* species = (const int*)d_in[16];
    float* out = (float*)d_out;

    k_group<<<1, 1024>>>(species);
    k_embS<<<NELEM, 32>>>(Ws1, bs1, Ws2, bs2);
    k_B<<<NFEAT, 256>>>(Wa1);
    k_edge<<<EDGES / 128, 128>>>(rij, Wr1, br1, Wr2, br2);
    k_atom<<<NATOM, 256>>>(fai);
    k_head<<<MAXG, 256>>>(ba1, Wa2, ba2, Wa3, ba3);
    k_final<<<1, 32>>>(out);
}

// round 3
// speedup vs baseline: 1.7925x; 1.4222x over previous
#include <cuda_runtime.h>
#include <math.h>

#define EDGES 65536
#define NATOM 2048
#define KTOT 69
#define NFEAT 216
#define NELEM 94
#define EMBD 16
#define H1D 256
#define H2D 128
#define MAXG 256
#define NACC 1680
#define TILE 32
#define SRPAD 34   // 32 edges + pad, 8B-aligned rows

// ---------------- scratch ----------------
__device__ __align__(16) float d_radialT[120 * EDGES];   // [m][e], m = rad*5+comp
__device__ __align__(16) float d_gijT[KTOT * EDGES];     // [k][e]
__device__ __align__(16) float d_feat[NATOM * NFEAT];
__device__ float d_embS[NELEM * EMBD];
__device__ __align__(16) float d_B[(size_t)NELEM * NFEAT * H1D]; // [s][f][o]
__device__ int   d_seg[NATOM + 1];
__device__ int   d_atom_order[NATOM];
__device__ int   d_grp_s[MAXG], d_grp_start[MAXG], d_grp_cnt[MAXG];
__device__ int   d_ngroups;
__device__ double d_partial[MAXG];

// ---------------- packed fp32x2 helpers ----------------
typedef unsigned long long u64;

__device__ __forceinline__ u64 splat2(float v) {
    u64 r; unsigned int u = __float_as_uint(v);
    asm("mov.b64 %0, {%1, %1};" : "=l"(r) : "r"(u));
    return r;
}
__device__ __forceinline__ void unpack2(u64 v, float& a, float& b) {
    unsigned int x, y;
    asm("mov.b64 {%0, %1}, %2;" : "=r"(x), "=r"(y) : "l"(v));
    a = __uint_as_float(x); b = __uint_as_float(y);
}
__device__ __forceinline__ void fma2(u64& d, u64 a, u64 b) {
    asm("fma.rn.f32x2 %0, %1, %2, %0;" : "+l"(d) : "l"(a), "l"(b));
}
__device__ __forceinline__ void add2(u64& d, u64 a) {
    asm("add.rn.f32x2 %0, %0, %1;" : "+l"(d) : "l"(a));
}

__device__ __forceinline__ float silu(float x) {
    return __fdividef(x, 1.0f + __expf(-x));
}

__device__ constexpr float ffact(int n) {
    return (n <= 1) ? 1.0f : (float)n * ffact(n - 1);
}

// ============================================================================
// per-edge radial MLP (f32x2) + angular factors ; transposed coalesced outputs
// ============================================================================
__global__ void __launch_bounds__(128, 5) k_edge(
    const float* __restrict__ rij,
    const float* __restrict__ Wr1, const float* __restrict__ br1,
    const float* __restrict__ Wr2, const float* __restrict__ br2)
{
    __shared__ __align__(16) float sW1[24 * 64];
    __shared__ __align__(16) float sB1[64];
    __shared__ __align__(16) float sW2[64 * 120];
    __shared__ __align__(16) float sB2[120];
    int tid = threadIdx.x;
    for (int i = tid; i < 24 * 64; i += 128) sW1[i] = Wr1[i];
    for (int i = tid; i < 64;      i += 128) sB1[i] = br1[i];
    for (int i = tid; i < 64 * 120; i += 128) sW2[i] = Wr2[i];
    for (int i = tid; i < 120;     i += 128) sB2[i] = br2[i];
    __syncthreads();

    int e = blockIdx.x * 128 + tid;

    float x = rij[e * 3 + 0], y = rij[e * 3 + 1], z = rij[e * 3 + 2];
    float r = sqrtf(x * x + y * y + z * z);
    float inv = 1.0f / r;
    float ux = x * inv, uy = y * inv, uz = z * inv;

    float rc = fminf(r, 6.0f);
    float fc = 0.5f * (cospif(rc * (1.0f / 6.0f)) + 1.0f);

    float basis[24];
#pragma unroll
    for (int i = 0; i < 24; i++) {
        float d = r - (float)i * (6.0f / 23.0f);
        basis[i] = __expf(-d * d * 8.0f) * fc;
    }

    // angular factors first (stores fire-and-forget, coalesced per k-row)
    {
        float px[5], py[5], pz[5];
        px[0]=1.0f; px[1]=ux+1e-12f; px[2]=px[1]*px[1]; px[3]=px[2]*px[1]; px[4]=px[2]*px[2];
        py[0]=1.0f; py[1]=uy+1e-12f; py[2]=py[1]*py[1]; py[3]=py[2]*py[1]; py[4]=py[2]*py[2];
        pz[0]=1.0f; pz[1]=uz+1e-12f; pz[2]=pz[1]*pz[1]; pz[3]=pz[2]*pz[1]; pz[4]=pz[2]*pz[2];
        int k = 0;
#pragma unroll
        for (int zz = 1; zz <= 4; zz++) {
#pragma unroll
            for (int n = 0; n <= zz; n++) {
#pragma unroll
                for (int lx = 0; lx <= n; lx++) {
#pragma unroll
                    for (int ly = 0; ly <= n - lx; ly++) {
                        int lz = n - lx - ly;
                        float fn = ffact(zz) / (ffact(zz - n) * ffact(lx) * ffact(ly) * ffact(lz));
                        d_gijT[(size_t)k * EDGES + e] = px[lx] * py[ly] * pz[lz] * fn;
                        k++;
                    }
                }
            }
        }
    }

    // layer 1: 24 -> 64 via FFMA2 (outputs paired in lanes)
    float h[64];
#pragma unroll
    for (int c8 = 0; c8 < 8; c8++) {
        const u64* bb = (const u64*)&sB1[c8 * 8];
        u64 a0 = bb[0], a1 = bb[1], a2 = bb[2], a3 = bb[3];
#pragma unroll
        for (int i = 0; i < 24; i++) {
            u64 bs = splat2(basis[i]);
            const ulonglong2* w = (const ulonglong2*)&sW1[i * 64 + c8 * 8];
            ulonglong2 w01 = w[0], w23 = w[1];
            fma2(a0, bs, w01.x); fma2(a1, bs, w01.y);
            fma2(a2, bs, w23.x); fma2(a3, bs, w23.y);
        }
        float f0, f1;
        unpack2(a0, f0, f1); h[c8*8+0] = silu(f0); h[c8*8+1] = silu(f1);
        unpack2(a1, f0, f1); h[c8*8+2] = silu(f0); h[c8*8+3] = silu(f1);
        unpack2(a2, f0, f1); h[c8*8+4] = silu(f0); h[c8*8+5] = silu(f1);
        unpack2(a3, f0, f1); h[c8*8+6] = silu(f0); h[c8*8+7] = silu(f1);
    }

    // layer 2: 64 -> 120 in 15 chunks of 8 outputs; coalesced transposed stores
#pragma unroll 1
    for (int c8 = 0; c8 < 15; c8++) {
        const u64* bb = (const u64*)&sB2[c8 * 8];
        u64 a0 = bb[0], a1 = bb[1], a2 = bb[2], a3 = bb[3];
#pragma unroll
        for (int j = 0; j < 64; j++) {
            u64 hs = splat2(h[j]);
            const ulonglong2* w = (const ulonglong2*)&sW2[j * 120 + c8 * 8];
            ulonglong2 w01 = w[0], w23 = w[1];
            fma2(a0, hs, w01.x); fma2(a1, hs, w01.y);
            fma2(a2, hs, w23.x); fma2(a3, hs, w23.y);
        }
        float f0, f1, f2, f3, f4, f5, f6, f7;
        unpack2(a0, f0, f1); unpack2(a1, f2, f3);
        unpack2(a2, f4, f5); unpack2(a3, f6, f7);
        float* ob = &d_radialT[(size_t)(c8 * 8) * EDGES + e];
        ob[0 * EDGES] = silu(f0); ob[1 * (size_t)EDGES] = silu(f1);
        ob[2 * (size_t)EDGES] = silu(f2); ob[3 * (size_t)EDGES] = silu(f3);
        ob[4 * (size_t)EDGES] = silu(f4); ob[5 * (size_t)EDGES] = silu(f5);
        ob[6 * (size_t)EDGES] = silu(f6); ob[7 * (size_t)EDGES] = silu(f7);
    }
}

// ============================================================================
// segment starts: d_seg[a] = first edge of atom a (fai sorted ascending)
// ============================================================================
__global__ void k_seg(const int* __restrict__ fai)
{
    int e = blockIdx.x * 256 + threadIdx.x;
    if (e >= EDGES) return;
    int f = fai[e];
    int fp = (e == 0) ? -1 : fai[e - 1];
    for (int a = fp + 1; a <= f; a++) d_seg[a] = e;
    if (e == EDGES - 1) {
        for (int a = f + 1; a <= NATOM; a++) d_seg[a] = EDGES;
    }
}

// ============================================================================
// per-atom segmented reduction (32-edge tiles, f32x2) + descriptor assembly
// ============================================================================
template <int Z>
__device__ __forceinline__ float zsum(const float* sgi, int rad, int sflag, int koff) {
    float sum = 0.0f;
    int k = koff;
#pragma unroll
    for (int n = 0; n <= Z; n++) {
        float lam = (n & 1) ? -1.0f : 1.0f;
#pragma unroll
        for (int lx = 0; lx <= n; lx++) {
#pragma unroll
            for (int ly = 0; ly <= n - lx; ly++) {
                float g = sgi[24 + k * 24 + rad];
                float g2 = g * g;
                sum += sflag ? g2 * lam : g2;
                k++;
            }
        }
    }
    return sum * (1.0f / (float)(1 << (Z - 1)));
}

__global__ void __launch_bounds__(256) k_atom()
{
    __shared__ __align__(16) float sr[120 * SRPAD];
    __shared__ __align__(16) float sg[KTOT * SRPAD];
    __shared__ float sgi[NACC];

    int a = blockIdx.x;
    int tid = threadIdx.x;
    int lo = d_seg[a], hi = d_seg[a + 1];

    // slot metadata (7 accumulators per thread); row m = rad*5+comp
    u64 acc2[7];
    int mIdx[7], kk[7];
    bool istb[7], valid[7];
#pragma unroll
    for (int jj = 0; jj < 7; jj++) {
        int ai = tid + jj * 256;
        valid[jj] = (ai < NACC);
        acc2[jj] = 0ull;
        if (ai < 24) { istb[jj] = true; mIdx[jj] = ai * 5; kk[jj] = 0; }
        else {
            istb[jj] = false;
            int t = ai - 24;
            int k = t / 24;
            int rad = t - k * 24;
            int comp = (k < 4) ? 1 : (k < 14) ? 2 : (k < 34) ? 3 : 4;
            mIdx[jj] = rad * 5 + comp;
            kk[jj] = k;
        }
    }

    for (int e0 = lo; e0 < hi; e0 += TILE) {
        // load 32 edges: rows coalesced from transposed globals; no divides
#pragma unroll 1
        for (int s = 0; s < 15; s++) {                 // 120*32/256
            int i = tid + s * 256;
            int m = i >> 5, ee = i & 31;
            int e = e0 + ee;
            sr[m * SRPAD + ee] = (e < hi) ? d_radialT[(size_t)m * EDGES + e] : 0.0f;
        }
#pragma unroll 1
        for (int s = 0; s < 9; s++) {                  // ceil(69*32/256)
            int i = tid + s * 256;
            if (i < KTOT * 32) {
                int k = i >> 5, ee = i & 31;
                int e = e0 + ee;
                sg[k * SRPAD + ee] = (e < hi) ? d_gijT[(size_t)k * EDGES + e] : 0.0f;
            }
        }
        __syncthreads();

#pragma unroll
        for (int jj = 0; jj < 7; jj++) {
            if (!valid[jj]) continue;
            const u64* rp = (const u64*)&sr[mIdx[jj] * SRPAD];
            if (istb[jj]) {
#pragma unroll
                for (int p = 0; p < 16; p++) add2(acc2[jj], rp[p]);
            } else {
                const u64* gp = (const u64*)&sg[kk[jj] * SRPAD];
#pragma unroll
                for (int p = 0; p < 16; p++) fma2(acc2[jj], rp[p], gp[p]);
            }
        }
        __syncthreads();
    }

#pragma unroll
    for (int jj = 0; jj < 7; jj++) {
        if (valid[jj]) {
            float l0, l1; unpack2(acc2[jj], l0, l1);
            sgi[tid + jj * 256] = l0 + l1;
        }
    }
    __syncthreads();

    if (tid < NFEAT) {
        float v;
        if (tid < 24) v = sgi[tid];
        else {
            int t = tid - 24;
            int iz = t / 48;
            int sflag = (t / 24) & 1;
            int rad = t % 24;
            if (iz == 0)      v = zsum<1>(sgi, rad, sflag, 0);
            else if (iz == 1) v = zsum<2>(sgi, rad, sflag, 4);
            else if (iz == 2) v = zsum<3>(sgi, rad, sflag, 14);
            else              v = zsum<4>(sgi, rad, sflag, 34);
        }
        d_feat[a * NFEAT + tid] = v;
    }
}

// ============================================================================
// species embedding + collapsed first-layer weights B[s][f][o]
// ============================================================================
__global__ void k_embS(const float* __restrict__ Ws1, const float* __restrict__ bs1,
                       const float* __restrict__ Ws2, const float* __restrict__ bs2)
{
    int s = blockIdx.x;
    int t = threadIdx.x;   // 32
    __shared__ float hh[32];
    hh[t] = silu(Ws1[s * 32 + t] + bs1[t]);
    __syncwarp();
    if (t < EMBD) {
        float a = bs2[t];
#pragma unroll
        for (int j = 0; j < 32; j++) a += hh[j] * Ws2[j * EMBD + t];
        d_embS[s * EMBD + t] = a;
    }
}

__global__ void __launch_bounds__(256) k_B(const float* __restrict__ Wa1)
{
    int f = blockIdx.x;      // 216
    int tid = threadIdx.x;   // 256
    __shared__ float sW[16 * 256];
    __shared__ float sE[NELEM * EMBD];
    for (int i = tid; i < 16 * 256; i += 256) sW[i] = Wa1[(size_t)(f * 16) * 256 + i];
    for (int i = tid; i < NELEM * EMBD; i += 256) sE[i] = d_embS[i];
    __syncthreads();
#pragma unroll 2
    for (int s = 0; s < NELEM; s++) {
        float acc = 0.0f;
#pragma unroll
        for (int m = 0; m < EMBD; m++) acc += sE[s * EMBD + m] * sW[m * 256 + tid];
        d_B[((size_t)s * NFEAT + f) * H1D + tid] = acc;
    }
}

// ============================================================================
// deterministic species grouping (single block)
// ============================================================================
__global__ void __launch_bounds__(1024) k_group(const int* __restrict__ sp)
{
    __shared__ int cnt[NELEM];
    __shared__ int off[NELEM];
    __shared__ int ssp[NATOM];
    int tid = threadIdx.x;
    if (tid < NELEM) cnt[tid] = 0;
    for (int a = tid; a < NATOM; a += 1024) ssp[a] = sp[a];
    __syncthreads();
    for (int a = tid; a < NATOM; a += 1024) atomicAdd(&cnt[ssp[a]], 1);
    __syncthreads();
    if (tid == 0) {
        int o = 0, ng = 0;
        for (int s = 0; s < NELEM; s++) {
            off[s] = o;
            int c = cnt[s];
            for (int ch = 0; ch < c; ch += 16) {
                d_grp_s[ng] = s; d_grp_start[ng] = o + ch;
                d_grp_cnt[ng] = min(16, c - ch); ng++;
            }
            o += c;
        }
        d_ngroups = ng;
    }
    for (int g = tid; g < MAXG; g += 1024) d_partial[g] = 0.0;
    __syncthreads();
    for (int a = tid; a < NATOM; a += 1024) {
        int s = ssp[a];
        int r = 0;
        for (int j = 0; j < a; j++) r += (ssp[j] == s);
        d_atom_order[off[s] + r] = a;
    }
}

// ============================================================================
// head MLP per species group (<=16 atoms), atoms packed in f32x2 lanes
// ============================================================================
__global__ void __launch_bounds__(256) k_head(
    const float* __restrict__ ba1,
    const float* __restrict__ Wa2, const float* __restrict__ ba2,
    const float* __restrict__ Wa3, const float* __restrict__ ba3)
{
    int g = blockIdx.x;
    if (g >= d_ngroups) return;
    int tid = threadIdx.x;

    __shared__ __align__(16) float sfeatT[NFEAT * 18];   // [f][atom]
    __shared__ __align__(16) float sh1T[H1D * 18];       // [j][atom]
    __shared__ __align__(16) float sh2T[H2D * 18];       // [o][atom]
    __shared__ double se[16];
    __shared__ int satom[16];

    int s = d_grp_s[g], start = d_grp_start[g], cnt = d_grp_cnt[g];
    if (tid < 16) satom[tid] = (tid < cnt) ? d_atom_order[start + tid] : 0;
    __syncthreads();

    for (int i = tid; i < 16 * NFEAT; i += 256) {
        int al = i / NFEAT, f = i - al * NFEAT;
        sfeatT[f * 18 + al] = (al < cnt) ? d_feat[(size_t)satom[al] * NFEAT + f] : 0.0f;
    }
    __syncthreads();

    // layer 1: 216 -> 256 ; thread = output neuron, 16 atoms as 8 pairs
    {
        u64 acc2[8];
        u64 binit = splat2(ba1[tid]);
#pragma unroll
        for (int p = 0; p < 8; p++) acc2[p] = binit;

        const float* Bs = &d_B[((size_t)s * NFEAT) * H1D + tid];
#pragma unroll 8
        for (int f = 0; f < NFEAT; f++) {
            u64 bw = splat2(__ldg(&Bs[(size_t)f * H1D]));
            const u64* fp = (const u64*)&sfeatT[f * 18];
#pragma unroll
            for (int p = 0; p < 8; p++) fma2(acc2[p], fp[p], bw);
        }
#pragma unroll
        for (int p = 0; p < 8; p++) {
            float lo, hi; unpack2(acc2[p], lo, hi);
            sh1T[tid * 18 + 2 * p]     = silu(lo);
            sh1T[tid * 18 + 2 * p + 1] = silu(hi);
        }
    }
    __syncthreads();

    // transpose sh1T rows are [j][atom] already? No: layer1 wrote [out j][atom] — correct.
    // layer 2: 256 -> 128 ; thread = (out o2, atom-half), 8 atoms as 4 pairs
    {
        int o2 = tid & 127;
        int half = tid >> 7;
        u64 acc2[4];
        u64 binit = splat2(ba2[o2]);
#pragma unroll
        for (int p = 0; p < 4; p++) acc2[p] = binit;
#pragma unroll 4
        for (int j = 0; j < H1D; j++) {
            u64 w = splat2(__ldg(&Wa2[j * H2D + o2]));
            const u64* hp = (const u64*)&sh1T[j * 18 + half * 8];
#pragma unroll
            for (int p = 0; p < 4; p++) fma2(acc2[p], hp[p], w);
        }
#pragma unroll
        for (int p = 0; p < 4; p++) {
            float lo, hi; unpack2(acc2[p], lo, hi);
            sh2T[o2 * 18 + half * 8 + 2 * p]     = silu(lo);
            sh2T[o2 * 18 + half * 8 + 2 * p + 1] = silu(hi);
        }
    }
    __syncthreads();

    if (tid < 16) {
        double ev = 0.0;
        if (tid < cnt) {
            float e3 = ba3[0];
#pragma unroll 4
            for (int j = 0; j < H2D; j++) e3 += sh2T[j * 18 + tid] * Wa3[j];
            ev = (double)e3;
        }
        se[tid] = ev;
    }
    __syncthreads();
    if (tid == 0) {
        double ssum = 0.0;
        for (int i = 0; i < 16; i++) ssum += se[i];
        d_partial[g] = ssum;
    }
}

__global__ void k_final(float* out) {
    int lane = threadIdx.x;
    double s = 0.0;
    for (int g = lane; g < MAXG; g += 32) s += d_partial[g];
#pragma unroll
    for (int o = 16; o > 0; o >>= 1) s += __shfl_down_sync(0xffffffffu, s, o);
    if (lane == 0) out[0] = (float)s;
}

// ============================================================================
extern "C" void kernel_launch(void* const* d_in, const int* in_sizes, int n_in,
                              void* d_out, int out_size)
{
    const float* rij = (const float*)d_in[0];
    const float* Wr1 = (const float*)d_in[1];
    const float* br1 = (const float*)d_in[2];
    const float* Wr2 = (const float*)d_in[3];
    const float* br2 = (const float*)d_in[4];
    const float* Ws1 = (const float*)d_in[5];
    const float* bs1 = (const float*)d_in[6];
    const float* Ws2 = (const float*)d_in[7];
    const float* bs2 = (const float*)d_in[8];
    const float* Wa1 = (const float*)d_in[9];
    const float* ba1 = (const float*)d_in[10];
    const float* Wa2 = (const float*)d_in[11];
    const float* ba2 = (const float*)d_in[12];
    const float* Wa3 = (const float*)d_in[13];
    const float* ba3 = (const float*)d_in[14];
    const int* fai = (const int*)d_in[15];
    const int* species = (const int*)d_in[16];
    float* out = (float*)d_out;

    k_group<<<1, 1024>>>(species);
    k_embS<<<NELEM, 32>>>(Ws1, bs1, Ws2, bs2);
    k_B<<<NFEAT, 256>>>(Wa1);
    k_seg<<<EDGES / 256, 256>>>(fai);
    k_edge<<<EDGES / 128, 128>>>(rij, Wr1, br1, Wr2, br2);
    k_atom<<<NATOM, 256>>>();
    k_head<<<MAXG, 256>>>(ba1, Wa2, ba2, Wa3, ba3);
    k_final<<<1, 32>>>(out);
}